// round 11
// baseline (speedup 1.0000x reference)
#include <cuda_runtime.h>
#include <cstdint>

#define SEQ 8192
#define DIM 512
#define D   64
#define BM  64
#define BN  64
#define NSPLIT 2
#define NITER (SEQ / NSPLIT / BN)   // 64

// ---------------- device scratch (no allocations allowed) -------------------
__device__ float    g_Q   [SEQ * D];      // fp32 row-major, scaled by 0.125*log2(e)
__device__ float    g_KhI [SEQ * D];      // tf32(K) hi, S B-frag interleaved layout
__device__ uint16_t g_KlB [SEQ * D];      // bf16(K - Kh), packed pairs (d, d+4)
__device__ float    g_VI  [SEQ * D];      // tf32(V), PV B-frag layout, plain key order
__device__ float g_Op[NSPLIT][SEQ * D];   // unnormalized partial O
__device__ float g_ms[NSPLIT][SEQ];       // row max (log2 units)
__device__ float g_ls[NSPLIT][SEQ];       // row sum

using u64 = unsigned long long;

// ---------------- PTX helpers ----------------------------------------------
__device__ __forceinline__ uint32_t smem_u32(const void* p) {
    uint32_t a;
    asm("{ .reg .u64 t; cvta.to.shared.u64 t, %1; cvt.u32.u64 %0, t; }" : "=r"(a) : "l"(p));
    return a;
}
__device__ __forceinline__ float tf32r(float x) {
    uint32_t u; asm("cvt.rna.tf32.f32 %0, %1;" : "=r"(u) : "f"(x));
    return __uint_as_float(u);
}
__device__ __forceinline__ float ex2(float x) {
    float y; asm("ex2.approx.f32 %0, %1;" : "=f"(y) : "f"(x)); return y;
}
__device__ __forceinline__ uint16_t bf16_rn(float x) {
    uint32_t u = __float_as_uint(x);
    uint32_t r = (u + 0x7FFFu + ((u >> 16) & 1u)) >> 16;
    return (uint16_t)r;
}
__device__ __forceinline__ void cp_async16(uint32_t dst, const void* src) {
    asm volatile("cp.async.cg.shared.global [%0], [%1], 16;" :: "r"(dst), "l"(src) : "memory");
}
#define CP_COMMIT() asm volatile("cp.async.commit_group;" ::: "memory")
#define CP_WAIT0()  asm volatile("cp.async.wait_group 0;" ::: "memory")

// m16n8k8 tf32 mma: D = A*B + D
__device__ __forceinline__ void mma8(float* d, const uint32_t* a, uint32_t b0, uint32_t b1) {
    asm volatile(
        "mma.sync.aligned.m16n8k8.row.col.f32.tf32.tf32.f32 "
        "{%0,%1,%2,%3}, {%4,%5,%6,%7}, {%8,%9}, {%0,%1,%2,%3};"
        : "+f"(d[0]), "+f"(d[1]), "+f"(d[2]), "+f"(d[3])
        : "r"(a[0]), "r"(a[1]), "r"(a[2]), "r"(a[3]), "r"(b0), "r"(b1));
}

// ---- packed f32x2 helpers (qkv kernel) ----
__device__ __forceinline__ u64 pack2(float lo, float hi) {
    u64 r; asm("mov.b64 %0, {%1, %2};" : "=l"(r) : "f"(lo), "f"(hi)); return r;
}
__device__ __forceinline__ u64 dup2(float v) { return pack2(v, v); }
__device__ __forceinline__ u64 ffma2(u64 a, u64 b, u64 c) {
    u64 d; asm("fma.rn.f32x2 %0, %1, %2, %3;" : "=l"(d) : "l"(a), "l"(b), "l"(c)); return d;
}
__device__ __forceinline__ float2 unpack2(u64 v) {
    float lo, hi; asm("mov.b64 {%0, %1}, %2;" : "=f"(lo), "=f"(hi) : "l"(v));
    return make_float2(lo, hi);
}

// ============================================================================
// QKV projection (fp32 FFMA2), register-prefetch + double smem buffer.
// grid.y: 0 -> g_Q (scaled by 0.125*log2e)
//         1 -> g_KhI (tf32 hi, frag layout) + g_KlB (bf16 lo, packed pairs)
//         2 -> g_VI  (tf32, plain within-chunk key order)
// ============================================================================
__global__ __launch_bounds__(256) void qkv_kernel(
    const float* __restrict__ X, const float* __restrict__ Wq,
    const float* __restrict__ Wk, const float* __restrict__ Wv)
{
    __shared__ float sX[2][32 * 68];  // [k][r]
    __shared__ float sW[2][32 * 68];  // [k][c]

    const int m = blockIdx.y;
    const float* __restrict__ W = (m == 0) ? Wq : (m == 1) ? Wk : Wv;
    const int row0 = blockIdx.x * 64;
    const int tid = threadIdx.x;
    const int tx = tid & 15, ty = tid >> 4;

    // X chunk map: c in [0,512): r=c>>3, k4=(c&7)*4; thread owns c=tid, tid+256
    const int xr0 = tid >> 3,          xk0 = (tid & 7) * 4;
    const int xr1 = (tid + 256) >> 3,  xk1 = xk0;
    // W chunk map: c in [0,512): k=c>>4, c4=(c&15)*4
    const int wk0 = tid >> 4,          wc0 = (tid & 15) * 4;
    const int wk1 = (tid + 256) >> 4,  wc1 = wc0;

    float4 rx0, rx1, rw0, rw1;
    auto ld = [&](int k0) {
        rx0 = *reinterpret_cast<const float4*>(&X[(row0 + xr0) * DIM + k0 + xk0]);
        rx1 = *reinterpret_cast<const float4*>(&X[(row0 + xr1) * DIM + k0 + xk1]);
        rw0 = *reinterpret_cast<const float4*>(&W[(k0 + wk0) * D + wc0]);
        rw1 = *reinterpret_cast<const float4*>(&W[(k0 + wk1) * D + wc1]);
    };
    auto st = [&](int b) {
        sX[b][(xk0 + 0) * 68 + xr0] = rx0.x; sX[b][(xk0 + 1) * 68 + xr0] = rx0.y;
        sX[b][(xk0 + 2) * 68 + xr0] = rx0.z; sX[b][(xk0 + 3) * 68 + xr0] = rx0.w;
        sX[b][(xk1 + 0) * 68 + xr1] = rx1.x; sX[b][(xk1 + 1) * 68 + xr1] = rx1.y;
        sX[b][(xk1 + 2) * 68 + xr1] = rx1.z; sX[b][(xk1 + 3) * 68 + xr1] = rx1.w;
        *reinterpret_cast<float4*>(&sW[b][wk0 * 68 + wc0]) = rw0;
        *reinterpret_cast<float4*>(&sW[b][wk1 * 68 + wc1]) = rw1;
    };

    u64 acc[4][2];
    #pragma unroll
    for (int r = 0; r < 4; r++) { acc[r][0] = 0ull; acc[r][1] = 0ull; }

    ld(0); st(0);
    __syncthreads();

    for (int blk = 0; blk < 16; blk++) {
        const int cur = blk & 1;
        if (blk + 1 < 16) ld((blk + 1) * 32);

        #pragma unroll 8
        for (int k = 0; k < 32; k++) {
            float4 a4 = *reinterpret_cast<const float4*>(&sX[cur][k * 68 + ty * 4]);
            ulonglong2 b = *reinterpret_cast<const ulonglong2*>(&sW[cur][k * 68 + tx * 4]);
            u64 A0 = dup2(a4.x), A1 = dup2(a4.y), A2 = dup2(a4.z), A3 = dup2(a4.w);
            acc[0][0] = ffma2(A0, b.x, acc[0][0]); acc[0][1] = ffma2(A0, b.y, acc[0][1]);
            acc[1][0] = ffma2(A1, b.x, acc[1][0]); acc[1][1] = ffma2(A1, b.y, acc[1][1]);
            acc[2][0] = ffma2(A2, b.x, acc[2][0]); acc[2][1] = ffma2(A2, b.y, acc[2][1]);
            acc[3][0] = ffma2(A3, b.x, acc[3][0]); acc[3][1] = ffma2(A3, b.y, acc[3][1]);
        }
        if (blk + 1 < 16) st((blk + 1) & 1);
        __syncthreads();
    }

    float f[4][4];
    #pragma unroll
    for (int r = 0; r < 4; r++) {
        float2 c01 = unpack2(acc[r][0]);
        float2 c23 = unpack2(acc[r][1]);
        f[r][0] = c01.x; f[r][1] = c01.y; f[r][2] = c23.x; f[r][3] = c23.y;
    }

    if (m == 0) {
        const float qscale = 0.125f * 1.4426950408889634f;
        #pragma unroll
        for (int r = 0; r < 4; r++)
            *reinterpret_cast<float4*>(&g_Q[(row0 + ty * 4 + r) * D + tx * 4]) =
                make_float4(f[r][0] * qscale, f[r][1] * qscale,
                            f[r][2] * qscale, f[r][3] * qscale);
    } else if (m == 1) {
        #pragma unroll
        for (int r = 0; r < 4; r++) {
            int key = row0 + ty * 4 + r;
            #pragma unroll
            for (int cc = 0; cc < 4; cc++) {
                int d = tx * 4 + cc;
                float h = tf32r(f[r][cc]);
                float l = f[r][cc] - h;
                int g = d >> 3;
                g_KhI[((g * SEQ + key) * 8) + (d & 3) * 2 + ((d >> 2) & 1)] = h;
                g_KlB[(((g * SEQ + key) * 4) + (d & 3)) * 2 + ((d >> 2) & 1)] = bf16_rn(l);
            }
        }
    } else {
        #pragma unroll
        for (int r = 0; r < 4; r++) {
            int key = row0 + ty * 4 + r;
            #pragma unroll
            for (int cc = 0; cc < 4; cc++) {
                int d = tx * 4 + cc;
                g_VI[(key >> 3) * 512 + d * 8 + (key & 7)] = tf32r(f[r][cc]);
            }
        }
    }
}

// ============================================================================
// Flash attention via mma.sync tf32. P register-resident.
// BM=64 (4 warps), 256 CTAs -> 2 CTAs/SM, one full wave on 148 SMs.
// smem per buffer: Kh 16KB | Kl(bf16) 8KB | V 16KB = 40KB, double buffered.
// ============================================================================
#define KVBUF_FLOATS 10240
#define ATTN_SMEM_BYTES (2 * KVBUF_FLOATS * 4)   // 81920

__device__ __forceinline__ void load_tiles(float* smbuf, int n0, int tid) {
    uint32_t sb = smem_u32(smbuf);
    const char* khp = (const char*)g_KhI;
    const char* klp = (const char*)g_KlB;
    const char* vp  = (const char*)g_VI;
    #pragma unroll
    for (int j = 0; j < 8; j++) {
        int c = tid + 128 * j;          // 0..1023
        int g = c >> 7, cw = c & 127;
        cp_async16(sb + c * 16, khp + ((size_t)(g * SEQ + n0)) * 32 + (size_t)cw * 16);
    }
    #pragma unroll
    for (int j = 0; j < 4; j++) {
        int c = tid + 128 * j;          // 0..511
        int g = c >> 6, cw = c & 63;
        cp_async16(sb + 16384 + c * 16, klp + ((size_t)(g * SEQ + n0)) * 16 + (size_t)cw * 16);
    }
    #pragma unroll
    for (int j = 0; j < 8; j++) {
        int c = tid + 128 * j;          // 0..1023
        cp_async16(sb + 24576 + c * 16, vp + (size_t)n0 * 256 + (size_t)c * 16);
    }
}

__global__ __launch_bounds__(128, 2) void attn_kernel()
{
    extern __shared__ float sm[];
    float* bufs = sm;                 // [2][KVBUF_FLOATS]
    const int tid  = threadIdx.x;
    const int warp = tid >> 5;
    const int lane = tid & 31;
    const int gid  = lane >> 2;
    const int tig  = lane & 3;
    const int q0 = blockIdx.x * BM;
    const int split = blockIdx.y;
    const int n_begin = split * (SEQ / NSPLIT);

    // ---- Q fragments (loop-invariant, registers) ----
    uint32_t qh[8][4], ql[8][4];
    {
        const float* qa = &g_Q[(q0 + warp * 16 + gid) * D];
        const float* qb = qa + 8 * D;
        #pragma unroll
        for (int g = 0; g < 8; g++) {
            float v0 = qa[8 * g + tig],     v2 = qa[8 * g + tig + 4];
            float v1 = qb[8 * g + tig],     v3 = qb[8 * g + tig + 4];
            float h;
            h = tf32r(v0); qh[g][0] = __float_as_uint(h); ql[g][0] = __float_as_uint(tf32r(v0 - h));
            h = tf32r(v1); qh[g][1] = __float_as_uint(h); ql[g][1] = __float_as_uint(tf32r(v1 - h));
            h = tf32r(v2); qh[g][2] = __float_as_uint(h); ql[g][2] = __float_as_uint(tf32r(v2 - h));
            h = tf32r(v3); qh[g][3] = __float_as_uint(h); ql[g][3] = __float_as_uint(tf32r(v3 - h));
        }
    }

    float oacc[8][4];
    #pragma unroll
    for (int nt = 0; nt < 8; nt++)
        #pragma unroll
        for (int c = 0; c < 4; c++) oacc[nt][c] = 0.0f;
    float mA = -INFINITY, mB = -INFINITY, lA = 0.0f, lB = 0.0f;

    load_tiles(bufs, n_begin, tid);
    CP_COMMIT();

    const int koff = gid * 8 + tig * 2;

    for (int i = 0; i < NITER; i++) {
        const int b = i & 1;
        float* kb = bufs + b * KVBUF_FLOATS;
        CP_WAIT0();
        __syncthreads();
        if (i + 1 < NITER)
            load_tiles(bufs + (b ^ 1) * KVBUF_FLOATS, n_begin + (i + 1) * BN, tid);
        CP_COMMIT();

        // ---- S = Qh*Kh + Ql*Kh + Qh*Kl ----
        float sacc[8][4];
        #pragma unroll
        for (int nt = 0; nt < 8; nt++)
            #pragma unroll
            for (int c = 0; c < 4; c++) sacc[nt][c] = 0.0f;

        const float* kh = kb;
        const uint32_t* klb = reinterpret_cast<const uint32_t*>(kb + 4096);
        #pragma unroll
        for (int g = 0; g < 8; g++) {
            #pragma unroll
            for (int nt = 0; nt < 8; nt++) {
                float2 bh = *reinterpret_cast<const float2*>(&kh[g * 512 + nt * 64 + koff]);
                uint32_t kk = klb[g * 256 + (nt * 8 + gid) * 4 + tig];
                uint32_t bh0 = __float_as_uint(bh.x), bh1 = __float_as_uint(bh.y);
                uint32_t bl0 = kk << 16, bl1 = kk & 0xFFFF0000u;
                mma8(sacc[nt], qh[g], bh0, bh1);
                mma8(sacc[nt], ql[g], bh0, bh1);
                mma8(sacc[nt], qh[g], bl0, bl1);
            }
        }

        // ---- online softmax; P (tf32-rounded) kept in registers ----
        float mxA = -INFINITY, mxB = -INFINITY;
        #pragma unroll
        for (int nt = 0; nt < 8; nt++) {
            mxA = fmaxf(mxA, fmaxf(sacc[nt][0], sacc[nt][1]));
            mxB = fmaxf(mxB, fmaxf(sacc[nt][2], sacc[nt][3]));
        }
        mxA = fmaxf(mxA, __shfl_xor_sync(0xffffffffu, mxA, 1));
        mxA = fmaxf(mxA, __shfl_xor_sync(0xffffffffu, mxA, 2));
        mxB = fmaxf(mxB, __shfl_xor_sync(0xffffffffu, mxB, 1));
        mxB = fmaxf(mxB, __shfl_xor_sync(0xffffffffu, mxB, 2));
        float mnA = fmaxf(mA, mxA), mnB = fmaxf(mB, mxB);
        float alA = ex2(mA - mnA),  alB = ex2(mB - mnB);
        mA = mnA; mB = mnB;

        uint32_t pf[8][4];
        float sumA = 0.0f, sumB = 0.0f;
        #pragma unroll
        for (int nt = 0; nt < 8; nt++) {
            float p0 = tf32r(ex2(sacc[nt][0] - mnA));
            float p1 = tf32r(ex2(sacc[nt][1] - mnA));
            float p2 = tf32r(ex2(sacc[nt][2] - mnB));
            float p3 = tf32r(ex2(sacc[nt][3] - mnB));
            sumA += p0 + p1; sumB += p2 + p3;
            pf[nt][0] = __float_as_uint(p0);
            pf[nt][1] = __float_as_uint(p2);
            pf[nt][2] = __float_as_uint(p1);
            pf[nt][3] = __float_as_uint(p3);
        }
        sumA += __shfl_xor_sync(0xffffffffu, sumA, 1);
        sumA += __shfl_xor_sync(0xffffffffu, sumA, 2);
        sumB += __shfl_xor_sync(0xffffffffu, sumB, 1);
        sumB += __shfl_xor_sync(0xffffffffu, sumB, 2);
        lA = lA * alA + sumA;
        lB = lB * alB + sumB;

        #pragma unroll
        for (int nt = 0; nt < 8; nt++) {
            oacc[nt][0] *= alA; oacc[nt][1] *= alA;
            oacc[nt][2] *= alB; oacc[nt][3] *= alB;
        }

        // ---- O += P * V ----
        const float* vv = kb + 6144;
        #pragma unroll
        for (int gk = 0; gk < 8; gk++) {
            #pragma unroll
            for (int nt = 0; nt < 8; nt++) {
                float2 bv = *reinterpret_cast<const float2*>(&vv[gk * 512 + nt * 64 + koff]);
                mma8(oacc[nt], pf[gk], __float_as_uint(bv.x), __float_as_uint(bv.y));
            }
        }
    }

    // ---- epilogue: unnormalized partials + stats ----
    int rowA = q0 + warp * 16 + gid;
    int rowB = rowA + 8;
    #pragma unroll
    for (int nt = 0; nt < 8; nt++) {
        *reinterpret_cast<float2*>(&g_Op[split][rowA * D + nt * 8 + 2 * tig]) =
            make_float2(oacc[nt][0], oacc[nt][1]);
        *reinterpret_cast<float2*>(&g_Op[split][rowB * D + nt * 8 + 2 * tig]) =
            make_float2(oacc[nt][2], oacc[nt][3]);
    }
    if (tig == 0) {
        g_ms[split][rowA] = mA; g_ls[split][rowA] = lA;
        g_ms[split][rowB] = mB; g_ls[split][rowB] = lB;
    }
}

// ============================================================================
// Merge the NSPLIT partials (stats in log2 units -> ex2).
// ============================================================================
__global__ __launch_bounds__(256) void merge_kernel(float* __restrict__ out)
{
    int idx = blockIdx.x * 256 + threadIdx.x;
    int row = idx >> 6;
    float m0 = g_ms[0][row], m1 = g_ms[1][row];
    float m = fmaxf(m0, m1);
    float e0 = ex2(m0 - m), e1 = ex2(m1 - m);
    float denom = e0 * g_ls[0][row] + e1 * g_ls[1][row];
    out[idx] = (e0 * g_Op[0][idx] + e1 * g_Op[1][idx]) / denom;
}

extern "C" void kernel_launch(void* const* d_in, const int* in_sizes, int n_in,
                              void* d_out, int out_size) {
    (void)in_sizes; (void)n_in; (void)out_size;
    const float* X  = (const float*)d_in[0];
    const float* Wq = (const float*)d_in[1];
    const float* Wk = (const float*)d_in[2];
    const float* Wv = (const float*)d_in[3];
    float* out = (float*)d_out;

    cudaFuncSetAttribute(attn_kernel,
                         cudaFuncAttributeMaxDynamicSharedMemorySize, ATTN_SMEM_BYTES);

    dim3 gqkv(SEQ / 64, 3);
    qkv_kernel<<<gqkv, 256>>>(X, Wq, Wk, Wv);

    dim3 gattn(SEQ / BM, NSPLIT);
    attn_kernel<<<gattn, 128, ATTN_SMEM_BYTES>>>();

    merge_kernel<<<SEQ * D / 256, 256>>>(out);
}

// round 13
// speedup vs baseline: 1.3224x; 1.3224x over previous
#include <cuda_runtime.h>
#include <cuda_fp16.h>
#include <cstdint>

#define SEQ 8192
#define DIM 512
#define D   64
#define BM  64
#define BN  64
#define NSPLIT 2
#define NITER (SEQ / NSPLIT / BN)   // 64

// ---------------- device scratch (no allocations allowed) -------------------
__device__ float    g_Q  [SEQ * D];       // fp32 row-major, scaled by 0.125*log2(e)
__device__ uint16_t g_KhH[SEQ * D];       // fp16(K) hi, m16n8k16 B-frag layout
__device__ uint16_t g_KlH[SEQ * D];       // fp16(K - Kh), same layout
__device__ uint16_t g_VhH[SEQ * D];       // fp16(V) hi, PV B-frag layout
__device__ uint16_t g_VlH[SEQ * D];       // fp16(V - Vh), same layout
__device__ float g_Op[NSPLIT][SEQ * D];   // unnormalized partial O
__device__ float g_ms[NSPLIT][SEQ];       // row max (log2 units)
__device__ float g_ls[NSPLIT][SEQ];       // row sum

using u64 = unsigned long long;

// ---------------- PTX helpers ----------------------------------------------
__device__ __forceinline__ uint32_t smem_u32(const void* p) {
    uint32_t a;
    asm("{ .reg .u64 t; cvta.to.shared.u64 t, %1; cvt.u32.u64 %0, t; }" : "=r"(a) : "l"(p));
    return a;
}
__device__ __forceinline__ float ex2(float x) {
    float y; asm("ex2.approx.f32 %0, %1;" : "=f"(y) : "f"(x)); return y;
}
__device__ __forceinline__ void cp_async16(uint32_t dst, const void* src) {
    asm volatile("cp.async.cg.shared.global [%0], [%1], 16;" :: "r"(dst), "l"(src) : "memory");
}
#define CP_COMMIT() asm volatile("cp.async.commit_group;" ::: "memory")
#define CP_WAIT0()  asm volatile("cp.async.wait_group 0;" ::: "memory")

// m16n8k16 fp16 mma, fp32 accumulate: D = A*B + D
__device__ __forceinline__ void mma16(float* d, const uint32_t* a, uint32_t b0, uint32_t b1) {
    asm volatile(
        "mma.sync.aligned.m16n8k16.row.col.f32.f16.f16.f32 "
        "{%0,%1,%2,%3}, {%4,%5,%6,%7}, {%8,%9}, {%0,%1,%2,%3};"
        : "+f"(d[0]), "+f"(d[1]), "+f"(d[2]), "+f"(d[3])
        : "r"(a[0]), "r"(a[1]), "r"(a[2]), "r"(a[3]), "r"(b0), "r"(b1));
}
__device__ __forceinline__ uint32_t h2bits(__half2 h) {
    return *reinterpret_cast<uint32_t*>(&h);
}
__device__ __forceinline__ uint2 lds64(uint32_t addr) {
    uint2 v;
    asm volatile("ld.shared.v2.u32 {%0, %1}, [%2];" : "=r"(v.x), "=r"(v.y) : "r"(addr));
    return v;
}

// ---- packed f32x2 helpers (qkv kernel) ----
__device__ __forceinline__ u64 pack2(float lo, float hi) {
    u64 r; asm("mov.b64 %0, {%1, %2};" : "=l"(r) : "f"(lo), "f"(hi)); return r;
}
__device__ __forceinline__ u64 dup2(float v) { return pack2(v, v); }
__device__ __forceinline__ u64 ffma2(u64 a, u64 b, u64 c) {
    u64 d; asm("fma.rn.f32x2 %0, %1, %2, %3;" : "=l"(d) : "l"(a), "l"(b), "l"(c)); return d;
}
__device__ __forceinline__ float2 unpack2(u64 v) {
    float lo, hi; asm("mov.b64 {%0, %1}, %2;" : "=f"(lo), "=f"(hi) : "l"(v));
    return make_float2(lo, hi);
}

// K/Kl u16 index: word = ((d&7)>>1)*2 + ((d>>3)&1); slot = d&1  (32B per (d-group, key))
__device__ __forceinline__ int k_idx(int key, int d) {
    return (((d >> 4) * SEQ + key) * 8 + ((d & 7) >> 1) * 2 + ((d >> 3) & 1)) * 2 + (d & 1);
}
// V u16 index: per 16-key chunk: word = ((key&7)>>1)*2 + ((key>>3)&1); slot = key&1
__device__ __forceinline__ int v_idx(int key, int d) {
    return (((key >> 4) * 512) + d * 8 + ((key & 7) >> 1) * 2 + ((key >> 3) & 1)) * 2 + (key & 1);
}

// ============================================================================
// QKV projection (fp32 FFMA2), register-prefetch + double smem buffer.
// ============================================================================
__global__ __launch_bounds__(256) void qkv_kernel(
    const float* __restrict__ X, const float* __restrict__ Wq,
    const float* __restrict__ Wk, const float* __restrict__ Wv)
{
    __shared__ float sX[2][32 * 68];
    __shared__ float sW[2][32 * 68];

    const int m = blockIdx.y;
    const float* __restrict__ W = (m == 0) ? Wq : (m == 1) ? Wk : Wv;
    const int row0 = blockIdx.x * 64;
    const int tid = threadIdx.x;
    const int tx = tid & 15, ty = tid >> 4;

    const int xr0 = tid >> 3,          xk0 = (tid & 7) * 4;
    const int xr1 = (tid + 256) >> 3;
    const int wk0 = tid >> 4,          wc0 = (tid & 15) * 4;
    const int wk1 = (tid + 256) >> 4;

    float4 rx0, rx1, rw0, rw1;
    auto ld = [&](int k0) {
        rx0 = *reinterpret_cast<const float4*>(&X[(row0 + xr0) * DIM + k0 + xk0]);
        rx1 = *reinterpret_cast<const float4*>(&X[(row0 + xr1) * DIM + k0 + xk0]);
        rw0 = *reinterpret_cast<const float4*>(&W[(k0 + wk0) * D + wc0]);
        rw1 = *reinterpret_cast<const float4*>(&W[(k0 + wk1) * D + wc0]);
    };
    auto st = [&](int b) {
        sX[b][(xk0 + 0) * 68 + xr0] = rx0.x; sX[b][(xk0 + 1) * 68 + xr0] = rx0.y;
        sX[b][(xk0 + 2) * 68 + xr0] = rx0.z; sX[b][(xk0 + 3) * 68 + xr0] = rx0.w;
        sX[b][(xk0 + 0) * 68 + xr1] = rx1.x; sX[b][(xk0 + 1) * 68 + xr1] = rx1.y;
        sX[b][(xk0 + 2) * 68 + xr1] = rx1.z; sX[b][(xk0 + 3) * 68 + xr1] = rx1.w;
        *reinterpret_cast<float4*>(&sW[b][wk0 * 68 + wc0]) = rw0;
        *reinterpret_cast<float4*>(&sW[b][wk1 * 68 + wc0]) = rw1;
    };

    u64 acc[4][2];
    #pragma unroll
    for (int r = 0; r < 4; r++) { acc[r][0] = 0ull; acc[r][1] = 0ull; }

    ld(0); st(0);
    __syncthreads();

    for (int blk = 0; blk < 16; blk++) {
        const int cur = blk & 1;
        if (blk + 1 < 16) ld((blk + 1) * 32);

        #pragma unroll 8
        for (int k = 0; k < 32; k++) {
            float4 a4 = *reinterpret_cast<const float4*>(&sX[cur][k * 68 + ty * 4]);
            ulonglong2 b = *reinterpret_cast<const ulonglong2*>(&sW[cur][k * 68 + tx * 4]);
            u64 A0 = dup2(a4.x), A1 = dup2(a4.y), A2 = dup2(a4.z), A3 = dup2(a4.w);
            acc[0][0] = ffma2(A0, b.x, acc[0][0]); acc[0][1] = ffma2(A0, b.y, acc[0][1]);
            acc[1][0] = ffma2(A1, b.x, acc[1][0]); acc[1][1] = ffma2(A1, b.y, acc[1][1]);
            acc[2][0] = ffma2(A2, b.x, acc[2][0]); acc[2][1] = ffma2(A2, b.y, acc[2][1]);
            acc[3][0] = ffma2(A3, b.x, acc[3][0]); acc[3][1] = ffma2(A3, b.y, acc[3][1]);
        }
        if (blk + 1 < 16) st((blk + 1) & 1);
        __syncthreads();
    }

    float f[4][4];
    #pragma unroll
    for (int r = 0; r < 4; r++) {
        float2 c01 = unpack2(acc[r][0]);
        float2 c23 = unpack2(acc[r][1]);
        f[r][0] = c01.x; f[r][1] = c01.y; f[r][2] = c23.x; f[r][3] = c23.y;
    }

    if (m == 0) {
        const float qscale = 0.125f * 1.4426950408889634f;
        #pragma unroll
        for (int r = 0; r < 4; r++)
            *reinterpret_cast<float4*>(&g_Q[(row0 + ty * 4 + r) * D + tx * 4]) =
                make_float4(f[r][0] * qscale, f[r][1] * qscale,
                            f[r][2] * qscale, f[r][3] * qscale);
    } else if (m == 1) {
        #pragma unroll
        for (int r = 0; r < 4; r++) {
            int key = row0 + ty * 4 + r;
            #pragma unroll
            for (int cc = 0; cc < 4; cc++) {
                int d = tx * 4 + cc;
                __half h = __float2half_rn(f[r][cc]);
                __half l = __float2half_rn(f[r][cc] - __half2float(h));
                int idx = k_idx(key, d);
                g_KhH[idx] = *reinterpret_cast<uint16_t*>(&h);
                g_KlH[idx] = *reinterpret_cast<uint16_t*>(&l);
            }
        }
    } else {
        #pragma unroll
        for (int r = 0; r < 4; r++) {
            int key = row0 + ty * 4 + r;
            #pragma unroll
            for (int cc = 0; cc < 4; cc++) {
                int d = tx * 4 + cc;
                __half h = __float2half_rn(f[r][cc]);
                __half l = __float2half_rn(f[r][cc] - __half2float(h));
                int idx = v_idx(key, d);
                g_VhH[idx] = *reinterpret_cast<uint16_t*>(&h);
                g_VlH[idx] = *reinterpret_cast<uint16_t*>(&l);
            }
        }
    }
}

// ============================================================================
// Flash attention via mma.sync m16n8k16 fp16 split precision. P register-resident.
// smem per buffer: Kh 8K | Kl 8K | Vh 8K | Vl 8K = 32KB, double buffered.
// ============================================================================
#define BUF_BYTES 32768u
#define ATTN_SMEM_BYTES (2u * BUF_BYTES)

__device__ __forceinline__ void load_tiles(uint32_t sb, int n0, int tid) {
    const char* khp = (const char*)g_KhH;
    const char* klp = (const char*)g_KlH;
    const char* vhp = (const char*)g_VhH;
    const char* vlp = (const char*)g_VlH;
    #pragma unroll
    for (int j = 0; j < 4; j++) {
        int c = tid + 128 * j;          // 0..511 chunks of 16B
        int dg = c >> 7, cw = c & 127;  // Kh/Kl: per d-group 64 keys x 32B
        size_t go = ((size_t)(dg * SEQ + n0)) * 32 + (size_t)cw * 16;
        cp_async16(sb + c * 16,          khp + go);
        cp_async16(sb + 8192 + c * 16,   klp + go);
        size_t gv = (size_t)n0 * 128 + (size_t)c * 16;  // V: contiguous 8KB
        cp_async16(sb + 16384 + c * 16,  vhp + gv);
        cp_async16(sb + 24576 + c * 16,  vlp + gv);
    }
}

__global__ __launch_bounds__(128, 2) void attn_kernel()
{
    extern __shared__ float sm[];
    const uint32_t sbase = smem_u32(sm);
    const int tid  = threadIdx.x;
    const int warp = tid >> 5;
    const int lane = tid & 31;
    const int gid  = lane >> 2;
    const int tig  = lane & 3;
    const int q0 = blockIdx.x * BM;
    const int split = blockIdx.y;
    const int n_begin = split * (SEQ / NSPLIT);

    // ---- Q fragments, fp16 hi/lo (loop-invariant registers) ----
    uint32_t qh[4][4], ql[4][4];
    {
        const float* qa = &g_Q[(q0 + warp * 16 + gid) * D];
        const float* qb = qa + 8 * D;
        #pragma unroll
        for (int kg = 0; kg < 4; kg++) {
            int d0 = kg * 16 + 2 * tig;
            #pragma unroll
            for (int hf = 0; hf < 2; hf++) {    // a0/a1, then a2/a3 (k +8)
                float va0 = qa[d0 + hf * 8], va1 = qa[d0 + hf * 8 + 1];
                float vb0 = qb[d0 + hf * 8], vb1 = qb[d0 + hf * 8 + 1];
                __half2 ha = __floats2half2_rn(va0, va1);
                __half2 hb = __floats2half2_rn(vb0, vb1);
                float2 fa = __half22float2(ha), fb = __half22float2(hb);
                __half2 la = __floats2half2_rn(va0 - fa.x, va1 - fa.y);
                __half2 lb = __floats2half2_rn(vb0 - fb.x, vb1 - fb.y);
                qh[kg][hf * 2 + 0] = h2bits(ha); qh[kg][hf * 2 + 1] = h2bits(hb);
                ql[kg][hf * 2 + 0] = h2bits(la); ql[kg][hf * 2 + 1] = h2bits(lb);
            }
        }
    }

    float oacc[8][4];
    #pragma unroll
    for (int dt = 0; dt < 8; dt++)
        #pragma unroll
        for (int c = 0; c < 4; c++) oacc[dt][c] = 0.0f;
    float mA = -INFINITY, mB = -INFINITY, lA = 0.0f, lB = 0.0f;

    load_tiles(sbase, n_begin, tid);
    CP_COMMIT();

    const uint32_t fragoff = (uint32_t)gid * 32 + (uint32_t)tig * 8;

    for (int i = 0; i < NITER; i++) {
        const uint32_t sb = sbase + (uint32_t)(i & 1) * BUF_BYTES;
        CP_WAIT0();
        __syncthreads();
        if (i + 1 < NITER)
            load_tiles(sbase + (uint32_t)((i + 1) & 1) * BUF_BYTES,
                       n_begin + (i + 1) * BN, tid);
        CP_COMMIT();

        // ---- S = Qh*Kh + Ql*Kh + Qh*Kl ----
        float sacc[8][4];
        #pragma unroll
        for (int nt = 0; nt < 8; nt++)
            #pragma unroll
            for (int c = 0; c < 4; c++) sacc[nt][c] = 0.0f;

        #pragma unroll
        for (int kg = 0; kg < 4; kg++) {
            #pragma unroll
            for (int nt = 0; nt < 8; nt++) {
                uint32_t base = sb + (uint32_t)kg * 2048 + (uint32_t)nt * 256 + fragoff;
                uint2 khb = lds64(base);
                uint2 klb = lds64(base + 8192);
                mma16(sacc[nt], qh[kg], khb.x, khb.y);
                mma16(sacc[nt], ql[kg], khb.x, khb.y);
                mma16(sacc[nt], qh[kg], klb.x, klb.y);
            }
        }

        // ---- online softmax; P packed to fp16 half2 in registers ----
        float mxA = -INFINITY, mxB = -INFINITY;
        #pragma unroll
        for (int nt = 0; nt < 8; nt++) {
            mxA = fmaxf(mxA, fmaxf(sacc[nt][0], sacc[nt][1]));
            mxB = fmaxf(mxB, fmaxf(sacc[nt][2], sacc[nt][3]));
        }
        mxA = fmaxf(mxA, __shfl_xor_sync(0xffffffffu, mxA, 1));
        mxA = fmaxf(mxA, __shfl_xor_sync(0xffffffffu, mxA, 2));
        mxB = fmaxf(mxB, __shfl_xor_sync(0xffffffffu, mxB, 1));
        mxB = fmaxf(mxB, __shfl_xor_sync(0xffffffffu, mxB, 2));
        float mnA = fmaxf(mA, mxA), mnB = fmaxf(mB, mxB);
        float alA = ex2(mA - mnA),  alB = ex2(mB - mnB);
        mA = mnA; mB = mnB;

        uint32_t pf0[8], pf1[8];
        float sumA = 0.0f, sumB = 0.0f;
        #pragma unroll
        for (int nt = 0; nt < 8; nt++) {
            float p0 = ex2(sacc[nt][0] - mnA);
            float p1 = ex2(sacc[nt][1] - mnA);
            float p2 = ex2(sacc[nt][2] - mnB);
            float p3 = ex2(sacc[nt][3] - mnB);
            __half2 h01 = __floats2half2_rn(p0, p1);   // row gid,  keys 2tig,2tig+1
            __half2 h23 = __floats2half2_rn(p2, p3);   // row gid+8
            pf0[nt] = h2bits(h01);
            pf1[nt] = h2bits(h23);
            float2 f01 = __half22float2(h01), f23 = __half22float2(h23);
            sumA += f01.x + f01.y;
            sumB += f23.x + f23.y;
        }
        sumA += __shfl_xor_sync(0xffffffffu, sumA, 1);
        sumA += __shfl_xor_sync(0xffffffffu, sumA, 2);
        sumB += __shfl_xor_sync(0xffffffffu, sumB, 1);
        sumB += __shfl_xor_sync(0xffffffffu, sumB, 2);
        lA = lA * alA + sumA;
        lB = lB * alB + sumB;

        #pragma unroll
        for (int dt = 0; dt < 8; dt++) {
            oacc[dt][0] *= alA; oacc[dt][1] *= alA;
            oacc[dt][2] *= alB; oacc[dt][3] *= alB;
        }

        // ---- O += P * (Vh + Vl)  (A-frag = packed S D-frags, register-resident) ----
        #pragma unroll
        for (int kg = 0; kg < 4; kg++) {
            uint32_t pa[4] = { pf0[2 * kg], pf1[2 * kg], pf0[2 * kg + 1], pf1[2 * kg + 1] };
            #pragma unroll
            for (int dt = 0; dt < 8; dt++) {
                uint32_t vb = sb + 16384 + (uint32_t)kg * 2048 + (uint32_t)dt * 256 + fragoff;
                uint2 vhb = lds64(vb);
                uint2 vlb = lds64(vb + 8192);
                mma16(oacc[dt], pa, vhb.x, vhb.y);
                mma16(oacc[dt], pa, vlb.x, vlb.y);
            }
        }
    }

    // ---- epilogue: unnormalized partials + stats ----
    int rowA = q0 + warp * 16 + gid;
    int rowB = rowA + 8;
    #pragma unroll
    for (int dt = 0; dt < 8; dt++) {
        *reinterpret_cast<float2*>(&g_Op[split][rowA * D + dt * 8 + 2 * tig]) =
            make_float2(oacc[dt][0], oacc[dt][1]);
        *reinterpret_cast<float2*>(&g_Op[split][rowB * D + dt * 8 + 2 * tig]) =
            make_float2(oacc[dt][2], oacc[dt][3]);
    }
    if (tig == 0) {
        g_ms[split][rowA] = mA; g_ls[split][rowA] = lA;
        g_ms[split][rowB] = mB; g_ls[split][rowB] = lB;
    }
}

// ============================================================================
// Merge the NSPLIT partials (stats in log2 units -> ex2).
// ============================================================================
__global__ __launch_bounds__(256) void merge_kernel(float* __restrict__ out)
{
    int idx = blockIdx.x * 256 + threadIdx.x;
    int row = idx >> 6;
    float m0 = g_ms[0][row], m1 = g_ms[1][row];
    float m = fmaxf(m0, m1);
    float e0 = ex2(m0 - m), e1 = ex2(m1 - m);
    float denom = e0 * g_ls[0][row] + e1 * g_ls[1][row];
    out[idx] = (e0 * g_Op[0][idx] + e1 * g_Op[1][idx]) / denom;
}

extern "C" void kernel_launch(void* const* d_in, const int* in_sizes, int n_in,
                              void* d_out, int out_size) {
    (void)in_sizes; (void)n_in; (void)out_size;
    const float* X  = (const float*)d_in[0];
    const float* Wq = (const float*)d_in[1];
    const float* Wk = (const float*)d_in[2];
    const float* Wv = (const float*)d_in[3];
    float* out = (float*)d_out;

    cudaFuncSetAttribute(attn_kernel,
                         cudaFuncAttributeMaxDynamicSharedMemorySize, ATTN_SMEM_BYTES);

    dim3 gqkv(SEQ / 64, 3);
    qkv_kernel<<<gqkv, 256>>>(X, Wq, Wk, Wv);

    dim3 gattn(SEQ / BM, NSPLIT);
    attn_kernel<<<gattn, 128, ATTN_SMEM_BYTES>>>();

    merge_kernel<<<SEQ * D / 256, 256>>>(out);
}

// round 14
// speedup vs baseline: 1.8406x; 1.3919x over previous
#include <cuda_runtime.h>
#include <cuda_fp16.h>
#include <cstdint>

#define SEQ 8192
#define DIM 512
#define D   64
#define BM  64
#define BN  64
#define NSPLIT 2
#define NITER (SEQ / NSPLIT / BN)   // 64
#define NCOL 192                    // [Q|K|V] combined output columns

// ---------------- device scratch (no allocations allowed) -------------------
__device__ float    g_Q  [SEQ * D];                     // fp32, scaled 0.125*log2e
__device__ __align__(16) uint16_t g_KhH[SEQ * D];       // fp16(K) hi, K-frag layout
__device__ __align__(16) uint16_t g_KlH[SEQ * D];       // fp16(K - Kh)
__device__ __align__(16) uint16_t g_VhH[SEQ * D];       // fp16(V), V-frag layout
__device__ __align__(16) uint16_t g_WhF[DIM * NCOL];    // fp16(W) hi, B-frag layout
__device__ __align__(16) uint16_t g_WlF[DIM * NCOL];    // fp16(W - Wh)
__device__ float g_Op[NSPLIT][SEQ * D];
__device__ float g_ms[NSPLIT][SEQ];
__device__ float g_ls[NSPLIT][SEQ];

// ---------------- PTX helpers ----------------------------------------------
__device__ __forceinline__ uint32_t smem_u32(const void* p) {
    uint32_t a;
    asm("{ .reg .u64 t; cvta.to.shared.u64 t, %1; cvt.u32.u64 %0, t; }" : "=r"(a) : "l"(p));
    return a;
}
__device__ __forceinline__ float ex2(float x) {
    float y; asm("ex2.approx.f32 %0, %1;" : "=f"(y) : "f"(x)); return y;
}
__device__ __forceinline__ void cp_async16(uint32_t dst, const void* src) {
    asm volatile("cp.async.cg.shared.global [%0], [%1], 16;" :: "r"(dst), "l"(src) : "memory");
}
#define CP_COMMIT() asm volatile("cp.async.commit_group;" ::: "memory")
#define CP_WAIT0()  asm volatile("cp.async.wait_group 0;" ::: "memory")

__device__ __forceinline__ void mma16(float* d, const uint32_t* a, uint32_t b0, uint32_t b1) {
    asm volatile(
        "mma.sync.aligned.m16n8k16.row.col.f32.f16.f16.f32 "
        "{%0,%1,%2,%3}, {%4,%5,%6,%7}, {%8,%9}, {%0,%1,%2,%3};"
        : "+f"(d[0]), "+f"(d[1]), "+f"(d[2]), "+f"(d[3])
        : "r"(a[0]), "r"(a[1]), "r"(a[2]), "r"(a[3]), "r"(b0), "r"(b1));
}
__device__ __forceinline__ uint32_t h2bits(__half2 h) {
    return *reinterpret_cast<uint32_t*>(&h);
}
__device__ __forceinline__ uint2 lds64(uint32_t addr) {
    uint2 v;
    asm volatile("ld.shared.v2.u32 {%0, %1}, [%2];" : "=r"(v.x), "=r"(v.y) : "r"(addr));
    return v;
}
__device__ __forceinline__ uint32_t packh2(float a, float b) {
    return h2bits(__floats2half2_rn(a, b));
}

// K/Kl u16 index (B-frag layout used by attn S): word/slot perm within 32B per (kg,key)
__device__ __forceinline__ int k_idx(int key, int d) {
    return (((d >> 4) * SEQ + key) * 8 + ((d & 7) >> 1) * 2 + ((d >> 3) & 1)) * 2 + (d & 1);
}
// V u16 index (B-frag layout used by attn PV)
__device__ __forceinline__ int v_idx(int key, int d) {
    return (((key >> 4) * 512) + d * 8 + ((key & 7) >> 1) * 2 + ((key >> 3) & 1)) * 2 + (key & 1);
}

// ============================================================================
// wconv: pack [Wq|Wk|Wv] -> fp16 hi/lo in B-frag layout over (col, k).
// One thread per (k-pair, col). 49152 threads.
// ============================================================================
__global__ __launch_bounds__(256) void wconv_kernel(
    const float* __restrict__ Wq, const float* __restrict__ Wk,
    const float* __restrict__ Wv)
{
    int idx = blockIdx.x * 256 + threadIdx.x;   // 0 .. 256*192-1
    int col = idx % NCOL;
    int k = (idx / NCOL) * 2;
    const float* src; int c2;
    if (col < 64)       { src = Wq; c2 = col; }
    else if (col < 128) { src = Wk; c2 = col - 64; }
    else                { src = Wv; c2 = col - 128; }
    float w0 = src[k * 64 + c2];
    float w1 = src[(k + 1) * 64 + c2];
    __half2 h = __floats2half2_rn(w0, w1);
    float2 hf = __half22float2(h);
    __half2 l = __floats2half2_rn(w0 - hf.x, w1 - hf.y);
    int word = ((k >> 4) * NCOL + col) * 8 + ((k & 7) >> 1) * 2 + ((k >> 3) & 1);
    reinterpret_cast<uint32_t*>(g_WhF)[word] = h2bits(h);
    reinterpret_cast<uint32_t*>(g_WlF)[word] = h2bits(l);
}

// ============================================================================
// qkv_tensor: C[8192, 192] = X[8192,512] @ W via fp16-split mma.sync.
// 128 CTAs x 512 threads; 64 rows/CTA; warp = (rowtile rt = w>>2, colgroup cg = w&3).
// k streamed in 16-wide groups, double-buffered cp.async. X converted to fp16
// hi/lo in registers at A-frag build. Epilogue scatters Q/Kh/Kl/Vh.
// ============================================================================
#define XPAD 20   // floats per staged row (80 B, 16B-aligned)

__global__ __launch_bounds__(512) void qkv_tensor(const float* __restrict__ X)
{
    __shared__ float    sXf[2][64 * XPAD];
    __shared__ uint16_t sWh[2][NCOL * 16];
    __shared__ uint16_t sWl[2][NCOL * 16];

    const int tid  = threadIdx.x;
    const int warp = tid >> 5;
    const int lane = tid & 31;
    const int gid  = lane >> 2;
    const int tig  = lane & 3;
    const int rt   = warp >> 2;
    const int cg   = warp & 3;
    const int row0 = blockIdx.x * 64;

    const uint32_t sx[2] = { smem_u32(sXf[0]), smem_u32(sXf[1]) };
    const uint32_t swh[2] = { smem_u32(sWh[0]), smem_u32(sWh[1]) };
    const uint32_t swl[2] = { smem_u32(sWl[0]), smem_u32(sWl[1]) };

    auto load = [&](int kg, int b) {
        #pragma unroll
        for (int j = 0; j < 2; j++) {
            int id = tid + 512 * j;              // 0..1023
            if (id < 256) {
                int r = id >> 2, part = id & 3;
                cp_async16(sx[b] + (uint32_t)(r * XPAD * 4 + part * 16),
                           X + (size_t)(row0 + r) * DIM + kg * 16 + part * 4);
            } else if (id < 640) {
                int c = id - 256;                // 0..383
                cp_async16(swh[b] + (uint32_t)c * 16,
                           (const char*)g_WhF + (size_t)kg * 6144 + (size_t)c * 16);
            } else {
                int c = id - 640;                // 0..383
                cp_async16(swl[b] + (uint32_t)c * 16,
                           (const char*)g_WlF + (size_t)kg * 6144 + (size_t)c * 16);
            }
        }
    };

    float oacc[6][4];
    #pragma unroll
    for (int nt = 0; nt < 6; nt++)
        #pragma unroll
        for (int c = 0; c < 4; c++) oacc[nt][c] = 0.0f;

    load(0, 0);
    CP_COMMIT();

    const int r0 = rt * 16 + gid;
    const int r1 = r0 + 8;

    for (int kg = 0; kg < 32; kg++) {
        const int b = kg & 1;
        CP_WAIT0();
        __syncthreads();
        if (kg + 1 < 32) { load(kg + 1, b ^ 1); CP_COMMIT(); }

        // ---- A frags: read X fp32 from staging, split to fp16 hi/lo ----
        const float* xs = sXf[b];
        float2 x00 = *reinterpret_cast<const float2*>(&xs[r0 * XPAD + 2 * tig]);
        float2 x01 = *reinterpret_cast<const float2*>(&xs[r0 * XPAD + 2 * tig + 8]);
        float2 x10 = *reinterpret_cast<const float2*>(&xs[r1 * XPAD + 2 * tig]);
        float2 x11 = *reinterpret_cast<const float2*>(&xs[r1 * XPAD + 2 * tig + 8]);
        uint32_t ah[4], al[4];
        {
            __half2 h; float2 f;
            h = __floats2half2_rn(x00.x, x00.y); f = __half22float2(h);
            ah[0] = h2bits(h); al[0] = packh2(x00.x - f.x, x00.y - f.y);
            h = __floats2half2_rn(x10.x, x10.y); f = __half22float2(h);
            ah[1] = h2bits(h); al[1] = packh2(x10.x - f.x, x10.y - f.y);
            h = __floats2half2_rn(x01.x, x01.y); f = __half22float2(h);
            ah[2] = h2bits(h); al[2] = packh2(x01.x - f.x, x01.y - f.y);
            h = __floats2half2_rn(x11.x, x11.y); f = __half22float2(h);
            ah[3] = h2bits(h); al[3] = packh2(x11.x - f.x, x11.y - f.y);
        }

        // ---- B frags + MMAs: S = Xh*Wh + Xl*Wh + Xh*Wl ----
        #pragma unroll
        for (int nt = 0; nt < 6; nt++) {
            uint32_t boff = (uint32_t)(cg * 48 + nt * 8 + gid) * 32 + (uint32_t)tig * 8;
            uint2 bh = lds64(swh[b] + boff);
            uint2 bl = lds64(swl[b] + boff);
            mma16(oacc[nt], ah, bh.x, bh.y);
            mma16(oacc[nt], al, bh.x, bh.y);
            mma16(oacc[nt], ah, bl.x, bl.y);
        }
    }

    // ---- epilogue: scatter to g_Q / g_KhH,g_KlH / g_VhH ----
    const float qscale = 0.125f * 1.4426950408889634f;
    #pragma unroll
    for (int nt = 0; nt < 6; nt++) {
        int c0 = cg * 48 + nt * 8 + 2 * tig;
        #pragma unroll
        for (int half = 0; half < 2; half++) {
            int row = row0 + (half ? r1 : r0);
            float v0 = oacc[nt][half ? 2 : 0];
            float v1 = oacc[nt][half ? 3 : 1];
            if (c0 < 64) {
                *reinterpret_cast<float2*>(&g_Q[row * D + c0]) =
                    make_float2(v0 * qscale, v1 * qscale);
            } else if (c0 < 128) {
                int d = c0 - 64;
                __half2 h = __floats2half2_rn(v0, v1);
                float2 hf = __half22float2(h);
                __half2 l = __floats2half2_rn(v0 - hf.x, v1 - hf.y);
                int word = ((d >> 4) * SEQ + row) * 8 + ((d & 7) >> 1) * 2 + ((d >> 3) & 1);
                reinterpret_cast<uint32_t*>(g_KhH)[word] = h2bits(h);
                reinterpret_cast<uint32_t*>(g_KlH)[word] = h2bits(l);
            } else {
                int d = c0 - 128;
                __half h0 = __float2half_rn(v0);
                __half h1 = __float2half_rn(v1);
                g_VhH[v_idx(row, d)]     = *reinterpret_cast<uint16_t*>(&h0);
                g_VhH[v_idx(row, d + 1)] = *reinterpret_cast<uint16_t*>(&h1);
            }
        }
    }
}

// ============================================================================
// Flash attention via mma.sync m16n8k16. Q/K fp16 2-term split, V single fp16.
// P register-resident. smem per buffer: Kh 8K | Kl 8K | Vh 8K = 24KB, x2.
// ============================================================================
#define BUF_BYTES 24576u
#define ATTN_SMEM_BYTES (2u * BUF_BYTES)

__device__ __forceinline__ void load_tiles(uint32_t sb, int n0, int tid) {
    const char* khp = (const char*)g_KhH;
    const char* klp = (const char*)g_KlH;
    const char* vhp = (const char*)g_VhH;
    #pragma unroll
    for (int j = 0; j < 4; j++) {
        int c = tid + 128 * j;          // 0..511 chunks of 16B
        int dg = c >> 7, cw = c & 127;
        size_t go = ((size_t)(dg * SEQ + n0)) * 32 + (size_t)cw * 16;
        cp_async16(sb + c * 16,         khp + go);
        cp_async16(sb + 8192 + c * 16,  klp + go);
        cp_async16(sb + 16384 + c * 16, vhp + (size_t)n0 * 128 + (size_t)c * 16);
    }
}

__global__ __launch_bounds__(128, 2) void attn_kernel()
{
    extern __shared__ float sm[];
    const uint32_t sbase = smem_u32(sm);
    const int tid  = threadIdx.x;
    const int warp = tid >> 5;
    const int lane = tid & 31;
    const int gid  = lane >> 2;
    const int tig  = lane & 3;
    const int q0 = blockIdx.x * BM;
    const int split = blockIdx.y;
    const int n_begin = split * (SEQ / NSPLIT);

    // ---- Q fragments, fp16 hi/lo (loop-invariant registers) ----
    uint32_t qh[4][4], ql[4][4];
    {
        const float* qa = &g_Q[(q0 + warp * 16 + gid) * D];
        const float* qb = qa + 8 * D;
        #pragma unroll
        for (int kg = 0; kg < 4; kg++) {
            int d0 = kg * 16 + 2 * tig;
            #pragma unroll
            for (int hf = 0; hf < 2; hf++) {
                float va0 = qa[d0 + hf * 8], va1 = qa[d0 + hf * 8 + 1];
                float vb0 = qb[d0 + hf * 8], vb1 = qb[d0 + hf * 8 + 1];
                __half2 ha = __floats2half2_rn(va0, va1);
                __half2 hb = __floats2half2_rn(vb0, vb1);
                float2 fa = __half22float2(ha), fb = __half22float2(hb);
                qh[kg][hf * 2 + 0] = h2bits(ha); qh[kg][hf * 2 + 1] = h2bits(hb);
                ql[kg][hf * 2 + 0] = packh2(va0 - fa.x, va1 - fa.y);
                ql[kg][hf * 2 + 1] = packh2(vb0 - fb.x, vb1 - fb.y);
            }
        }
    }

    float oacc[8][4];
    #pragma unroll
    for (int dt = 0; dt < 8; dt++)
        #pragma unroll
        for (int c = 0; c < 4; c++) oacc[dt][c] = 0.0f;
    float mA = -INFINITY, mB = -INFINITY, lA = 0.0f, lB = 0.0f;

    load_tiles(sbase, n_begin, tid);
    CP_COMMIT();

    const uint32_t fragoff = (uint32_t)gid * 32 + (uint32_t)tig * 8;

    for (int i = 0; i < NITER; i++) {
        const uint32_t sb = sbase + (uint32_t)(i & 1) * BUF_BYTES;
        CP_WAIT0();
        __syncthreads();
        if (i + 1 < NITER)
            load_tiles(sbase + (uint32_t)((i + 1) & 1) * BUF_BYTES,
                       n_begin + (i + 1) * BN, tid);
        CP_COMMIT();

        // ---- S = Qh*Kh + Ql*Kh + Qh*Kl ----
        float sacc[8][4];
        #pragma unroll
        for (int nt = 0; nt < 8; nt++)
            #pragma unroll
            for (int c = 0; c < 4; c++) sacc[nt][c] = 0.0f;

        #pragma unroll
        for (int kg = 0; kg < 4; kg++) {
            #pragma unroll
            for (int nt = 0; nt < 8; nt++) {
                uint32_t base = sb + (uint32_t)kg * 2048 + (uint32_t)nt * 256 + fragoff;
                uint2 khb = lds64(base);
                uint2 klb = lds64(base + 8192);
                mma16(sacc[nt], qh[kg], khb.x, khb.y);
                mma16(sacc[nt], ql[kg], khb.x, khb.y);
                mma16(sacc[nt], qh[kg], klb.x, klb.y);
            }
        }

        // ---- online softmax; P packed to fp16 half2 in registers ----
        float mxA = -INFINITY, mxB = -INFINITY;
        #pragma unroll
        for (int nt = 0; nt < 8; nt++) {
            mxA = fmaxf(mxA, fmaxf(sacc[nt][0], sacc[nt][1]));
            mxB = fmaxf(mxB, fmaxf(sacc[nt][2], sacc[nt][3]));
        }
        mxA = fmaxf(mxA, __shfl_xor_sync(0xffffffffu, mxA, 1));
        mxA = fmaxf(mxA, __shfl_xor_sync(0xffffffffu, mxA, 2));
        mxB = fmaxf(mxB, __shfl_xor_sync(0xffffffffu, mxB, 1));
        mxB = fmaxf(mxB, __shfl_xor_sync(0xffffffffu, mxB, 2));
        float mnA = fmaxf(mA, mxA), mnB = fmaxf(mB, mxB);
        float alA = ex2(mA - mnA),  alB = ex2(mB - mnB);
        mA = mnA; mB = mnB;

        uint32_t pf0[8], pf1[8];
        float sumA = 0.0f, sumB = 0.0f;
        #pragma unroll
        for (int nt = 0; nt < 8; nt++) {
            float p0 = ex2(sacc[nt][0] - mnA);
            float p1 = ex2(sacc[nt][1] - mnA);
            float p2 = ex2(sacc[nt][2] - mnB);
            float p3 = ex2(sacc[nt][3] - mnB);
            __half2 h01 = __floats2half2_rn(p0, p1);
            __half2 h23 = __floats2half2_rn(p2, p3);
            pf0[nt] = h2bits(h01);
            pf1[nt] = h2bits(h23);
            float2 f01 = __half22float2(h01), f23 = __half22float2(h23);
            sumA += f01.x + f01.y;
            sumB += f23.x + f23.y;
        }
        sumA += __shfl_xor_sync(0xffffffffu, sumA, 1);
        sumA += __shfl_xor_sync(0xffffffffu, sumA, 2);
        sumB += __shfl_xor_sync(0xffffffffu, sumB, 1);
        sumB += __shfl_xor_sync(0xffffffffu, sumB, 2);
        lA = lA * alA + sumA;
        lB = lB * alB + sumB;

        #pragma unroll
        for (int dt = 0; dt < 8; dt++) {
            oacc[dt][0] *= alA; oacc[dt][1] *= alA;
            oacc[dt][2] *= alB; oacc[dt][3] *= alB;
        }

        // ---- O += P * Vh  (A-frag = packed S D-frags, register-resident) ----
        #pragma unroll
        for (int kg = 0; kg < 4; kg++) {
            uint32_t pa[4] = { pf0[2 * kg], pf1[2 * kg], pf0[2 * kg + 1], pf1[2 * kg + 1] };
            #pragma unroll
            for (int dt = 0; dt < 8; dt++) {
                uint32_t vb = sb + 16384 + (uint32_t)kg * 2048 + (uint32_t)dt * 256 + fragoff;
                uint2 vhb = lds64(vb);
                mma16(oacc[dt], pa, vhb.x, vhb.y);
            }
        }
    }

    // ---- epilogue: unnormalized partials + stats ----
    int rowA = q0 + warp * 16 + gid;
    int rowB = rowA + 8;
    #pragma unroll
    for (int dt = 0; dt < 8; dt++) {
        *reinterpret_cast<float2*>(&g_Op[split][rowA * D + dt * 8 + 2 * tig]) =
            make_float2(oacc[dt][0], oacc[dt][1]);
        *reinterpret_cast<float2*>(&g_Op[split][rowB * D + dt * 8 + 2 * tig]) =
            make_float2(oacc[dt][2], oacc[dt][3]);
    }
    if (tig == 0) {
        g_ms[split][rowA] = mA; g_ls[split][rowA] = lA;
        g_ms[split][rowB] = mB; g_ls[split][rowB] = lB;
    }
}

// ============================================================================
// Merge the NSPLIT partials (stats in log2 units -> ex2).
// ============================================================================
__global__ __launch_bounds__(256) void merge_kernel(float* __restrict__ out)
{
    int idx = blockIdx.x * 256 + threadIdx.x;
    int row = idx >> 6;
    float m0 = g_ms[0][row], m1 = g_ms[1][row];
    float m = fmaxf(m0, m1);
    float e0 = ex2(m0 - m), e1 = ex2(m1 - m);
    float denom = e0 * g_ls[0][row] + e1 * g_ls[1][row];
    out[idx] = (e0 * g_Op[0][idx] + e1 * g_Op[1][idx]) / denom;
}

extern "C" void kernel_launch(void* const* d_in, const int* in_sizes, int n_in,
                              void* d_out, int out_size) {
    (void)in_sizes; (void)n_in; (void)out_size;
    const float* X  = (const float*)d_in[0];
    const float* Wq = (const float*)d_in[1];
    const float* Wk = (const float*)d_in[2];
    const float* Wv = (const float*)d_in[3];
    float* out = (float*)d_out;

    cudaFuncSetAttribute(attn_kernel,
                         cudaFuncAttributeMaxDynamicSharedMemorySize, ATTN_SMEM_BYTES);

    wconv_kernel<<<(256 * NCOL) / 256, 256>>>(Wq, Wk, Wv);
    qkv_tensor<<<SEQ / 64, 512>>>(X);

    dim3 gattn(SEQ / BM, NSPLIT);
    attn_kernel<<<gattn, 128, ATTN_SMEM_BYTES>>>();

    merge_kernel<<<SEQ * D / 256, 256>>>(out);
}

// round 15
// speedup vs baseline: 1.9608x; 1.0653x over previous
#include <cuda_runtime.h>
#include <cuda_fp16.h>
#include <cstdint>

#define SEQ 8192
#define DIM 512
#define D   64
#define BM  64
#define BN  128
#define NSPLIT 2
#define NITER (SEQ / NSPLIT / BN)   // 32
#define NCOL 192                    // [Q|K|V] combined output columns

// ---------------- device scratch (no allocations allowed) -------------------
__device__ float    g_Q  [SEQ * D];                     // fp32, scaled 0.125*log2e
__device__ __align__(16) uint16_t g_KC [SEQ * D * 2];   // fp16 K hi+lo fused frag tile
__device__ __align__(16) uint16_t g_VhH[SEQ * D];       // fp16(V), V-frag layout
__device__ __align__(16) uint16_t g_WhF[DIM * NCOL];    // fp16(W) hi, B-frag layout
__device__ __align__(16) uint16_t g_WlF[DIM * NCOL];    // fp16(W - Wh)
__device__ float g_Op[NSPLIT][SEQ * D];
__device__ float g_ms[NSPLIT][SEQ];
__device__ float g_ls[NSPLIT][SEQ];

// ---------------- PTX helpers ----------------------------------------------
__device__ __forceinline__ uint32_t smem_u32(const void* p) {
    uint32_t a;
    asm("{ .reg .u64 t; cvta.to.shared.u64 t, %1; cvt.u32.u64 %0, t; }" : "=r"(a) : "l"(p));
    return a;
}
__device__ __forceinline__ float ex2(float x) {
    float y; asm("ex2.approx.f32 %0, %1;" : "=f"(y) : "f"(x)); return y;
}
__device__ __forceinline__ uint32_t ex2h2(uint32_t x) {
    uint32_t y; asm("ex2.approx.f16x2 %0, %1;" : "=r"(y) : "r"(x)); return y;
}
__device__ __forceinline__ void cp_async16(uint32_t dst, const void* src) {
    asm volatile("cp.async.cg.shared.global [%0], [%1], 16;" :: "r"(dst), "l"(src) : "memory");
}
#define CP_COMMIT() asm volatile("cp.async.commit_group;" ::: "memory")
#define CP_WAIT0()  asm volatile("cp.async.wait_group 0;" ::: "memory")

__device__ __forceinline__ void mma16(float* d, const uint32_t* a, uint32_t b0, uint32_t b1) {
    asm volatile(
        "mma.sync.aligned.m16n8k16.row.col.f32.f16.f16.f32 "
        "{%0,%1,%2,%3}, {%4,%5,%6,%7}, {%8,%9}, {%0,%1,%2,%3};"
        : "+f"(d[0]), "+f"(d[1]), "+f"(d[2]), "+f"(d[3])
        : "r"(a[0]), "r"(a[1]), "r"(a[2]), "r"(a[3]), "r"(b0), "r"(b1));
}
__device__ __forceinline__ uint32_t h2bits(__half2 h) {
    return *reinterpret_cast<uint32_t*>(&h);
}
__device__ __forceinline__ uint2 lds64(uint32_t addr) {
    uint2 v;
    asm volatile("ld.shared.v2.u32 {%0, %1}, [%2];" : "=r"(v.x), "=r"(v.y) : "r"(addr));
    return v;
}
__device__ __forceinline__ uint4 lds128(uint32_t addr) {
    uint4 v;
    asm volatile("ld.shared.v4.u32 {%0,%1,%2,%3}, [%4];"
                 : "=r"(v.x), "=r"(v.y), "=r"(v.z), "=r"(v.w) : "r"(addr));
    return v;
}
__device__ __forceinline__ uint32_t packh2(float a, float b) {
    return h2bits(__floats2half2_rn(a, b));
}

// V u16 index (B-frag layout used by attn PV)
__device__ __forceinline__ int v_idx(int key, int d) {
    return (((key >> 4) * 512) + d * 8 + ((key & 7) >> 1) * 2 + ((key >> 3) & 1)) * 2 + (key & 1);
}

// ============================================================================
// wconv: pack [Wq|Wk|Wv] -> fp16 hi/lo in B-frag layout over (col, k).
// ============================================================================
__global__ __launch_bounds__(256) void wconv_kernel(
    const float* __restrict__ Wq, const float* __restrict__ Wk,
    const float* __restrict__ Wv)
{
    int idx = blockIdx.x * 256 + threadIdx.x;   // 0 .. 256*192-1
    int col = idx % NCOL;
    int k = (idx / NCOL) * 2;
    const float* src; int c2;
    if (col < 64)       { src = Wq; c2 = col; }
    else if (col < 128) { src = Wk; c2 = col - 64; }
    else                { src = Wv; c2 = col - 128; }
    float w0 = src[k * 64 + c2];
    float w1 = src[(k + 1) * 64 + c2];
    __half2 h = __floats2half2_rn(w0, w1);
    float2 hf = __half22float2(h);
    __half2 l = __floats2half2_rn(w0 - hf.x, w1 - hf.y);
    int word = ((k >> 4) * NCOL + col) * 8 + ((k & 7) >> 1) * 2 + ((k >> 3) & 1);
    reinterpret_cast<uint32_t*>(g_WhF)[word] = h2bits(h);
    reinterpret_cast<uint32_t*>(g_WlF)[word] = h2bits(l);
}

// ============================================================================
// qkv_tensor: C[8192, 192] = X[8192,512] @ W via fp16-split mma.sync.
// 128 CTAs x 512 threads; 64 rows/CTA. Epilogue scatters Q / fused-KC / Vh.
// ============================================================================
#define XPAD 20

__global__ __launch_bounds__(512) void qkv_tensor(const float* __restrict__ X)
{
    __shared__ float    sXf[2][64 * XPAD];
    __shared__ uint16_t sWh[2][NCOL * 16];
    __shared__ uint16_t sWl[2][NCOL * 16];

    const int tid  = threadIdx.x;
    const int warp = tid >> 5;
    const int lane = tid & 31;
    const int gid  = lane >> 2;
    const int tig  = lane & 3;
    const int rt   = warp >> 2;
    const int cg   = warp & 3;
    const int row0 = blockIdx.x * 64;

    const uint32_t sx[2]  = { smem_u32(sXf[0]), smem_u32(sXf[1]) };
    const uint32_t swh[2] = { smem_u32(sWh[0]), smem_u32(sWh[1]) };
    const uint32_t swl[2] = { smem_u32(sWl[0]), smem_u32(sWl[1]) };

    auto load = [&](int kg, int b) {
        #pragma unroll
        for (int j = 0; j < 2; j++) {
            int id = tid + 512 * j;
            if (id < 256) {
                int r = id >> 2, part = id & 3;
                cp_async16(sx[b] + (uint32_t)(r * XPAD * 4 + part * 16),
                           X + (size_t)(row0 + r) * DIM + kg * 16 + part * 4);
            } else if (id < 640) {
                int c = id - 256;
                cp_async16(swh[b] + (uint32_t)c * 16,
                           (const char*)g_WhF + (size_t)kg * 6144 + (size_t)c * 16);
            } else {
                int c = id - 640;
                cp_async16(swl[b] + (uint32_t)c * 16,
                           (const char*)g_WlF + (size_t)kg * 6144 + (size_t)c * 16);
            }
        }
    };

    float oacc[6][4];
    #pragma unroll
    for (int nt = 0; nt < 6; nt++)
        #pragma unroll
        for (int c = 0; c < 4; c++) oacc[nt][c] = 0.0f;

    load(0, 0);
    CP_COMMIT();

    const int r0 = rt * 16 + gid;
    const int r1 = r0 + 8;

    for (int kg = 0; kg < 32; kg++) {
        const int b = kg & 1;
        CP_WAIT0();
        __syncthreads();
        if (kg + 1 < 32) { load(kg + 1, b ^ 1); CP_COMMIT(); }

        const float* xs = sXf[b];
        float2 x00 = *reinterpret_cast<const float2*>(&xs[r0 * XPAD + 2 * tig]);
        float2 x01 = *reinterpret_cast<const float2*>(&xs[r0 * XPAD + 2 * tig + 8]);
        float2 x10 = *reinterpret_cast<const float2*>(&xs[r1 * XPAD + 2 * tig]);
        float2 x11 = *reinterpret_cast<const float2*>(&xs[r1 * XPAD + 2 * tig + 8]);
        uint32_t ah[4], al[4];
        {
            __half2 h; float2 f;
            h = __floats2half2_rn(x00.x, x00.y); f = __half22float2(h);
            ah[0] = h2bits(h); al[0] = packh2(x00.x - f.x, x00.y - f.y);
            h = __floats2half2_rn(x10.x, x10.y); f = __half22float2(h);
            ah[1] = h2bits(h); al[1] = packh2(x10.x - f.x, x10.y - f.y);
            h = __floats2half2_rn(x01.x, x01.y); f = __half22float2(h);
            ah[2] = h2bits(h); al[2] = packh2(x01.x - f.x, x01.y - f.y);
            h = __floats2half2_rn(x11.x, x11.y); f = __half22float2(h);
            ah[3] = h2bits(h); al[3] = packh2(x11.x - f.x, x11.y - f.y);
        }

        #pragma unroll
        for (int nt = 0; nt < 6; nt++) {
            uint32_t boff = (uint32_t)(cg * 48 + nt * 8 + gid) * 32 + (uint32_t)tig * 8;
            uint2 bh = lds64(swh[b] + boff);
            uint2 bl = lds64(swl[b] + boff);
            mma16(oacc[nt], ah, bh.x, bh.y);
            mma16(oacc[nt], al, bh.x, bh.y);
            mma16(oacc[nt], ah, bl.x, bl.y);
        }
    }

    // ---- epilogue: scatter to g_Q / g_KC (fused hi/lo) / g_VhH ----
    const float qscale = 0.125f * 1.4426950408889634f;
    #pragma unroll
    for (int nt = 0; nt < 6; nt++) {
        int c0 = cg * 48 + nt * 8 + 2 * tig;
        #pragma unroll
        for (int half = 0; half < 2; half++) {
            int row = row0 + (half ? r1 : r0);
            float v0 = oacc[nt][half ? 2 : 0];
            float v1 = oacc[nt][half ? 3 : 1];
            if (c0 < 64) {
                *reinterpret_cast<float2*>(&g_Q[row * D + c0]) =
                    make_float2(v0 * qscale, v1 * qscale);
            } else if (c0 < 128) {
                int d = c0 - 64;
                __half2 h = __floats2half2_rn(v0, v1);
                float2 hf = __half22float2(h);
                __half2 l = __floats2half2_rn(v0 - hf.x, v1 - hf.y);
                int base = ((d >> 4) * SEQ + row) * 16;      // word32 units (64B/block)
                int w = ((d & 7) >> 1) * 2 + ((d >> 3) & 1);
                int p = w >> 1, s = w & 1;
                uint32_t* kc = reinterpret_cast<uint32_t*>(g_KC);
                kc[base + p * 4 + s]     = h2bits(h);
                kc[base + p * 4 + 2 + s] = h2bits(l);
            } else {
                int d = c0 - 128;
                __half h0 = __float2half_rn(v0);
                __half h1 = __float2half_rn(v1);
                g_VhH[v_idx(row, d)]     = *reinterpret_cast<uint16_t*>(&h0);
                g_VhH[v_idx(row, d + 1)] = *reinterpret_cast<uint16_t*>(&h1);
            }
        }
    }
}

// ============================================================================
// Flash attention, m16n8k16 fp16 split. BN=128, fused KhKl LDS.128 tile,
// ex2.approx.f16x2 softmax, P register-resident.
// smem per buffer: KC 32KB | Vh 16KB = 48KB, double buffered = 96KB.
// ============================================================================
#define BUF_BYTES 49152u
#define VOFF 32768u
#define ATTN_SMEM_BYTES (2u * BUF_BYTES)

__device__ __forceinline__ void load_tiles(uint32_t sb, int n0, int tid) {
    const char* kcp = (const char*)g_KC;
    const char* vhp = (const char*)g_VhH;
    #pragma unroll
    for (int j = 0; j < 16; j++) {
        int c = tid + 128 * j;            // 0..2047 chunks of 16B
        int dg = c >> 9, cw = c & 511;    // per dg: 128 keys x 64B contiguous
        cp_async16(sb + c * 16, kcp + ((size_t)(dg * SEQ + n0)) * 64 + (size_t)cw * 16);
    }
    #pragma unroll
    for (int j = 0; j < 8; j++) {
        int c = tid + 128 * j;            // 0..1023
        cp_async16(sb + VOFF + c * 16, vhp + (size_t)n0 * 128 + (size_t)c * 16);
    }
}

__global__ __launch_bounds__(128, 2) void attn_kernel()
{
    extern __shared__ float sm[];
    const uint32_t sbase = smem_u32(sm);
    const int tid  = threadIdx.x;
    const int warp = tid >> 5;
    const int lane = tid & 31;
    const int gid  = lane >> 2;
    const int tig  = lane & 3;
    const int q0 = blockIdx.x * BM;
    const int split = blockIdx.y;
    const int n_begin = split * (SEQ / NSPLIT);

    // ---- Q fragments, fp16 hi/lo (loop-invariant registers) ----
    uint32_t qh[4][4], ql[4][4];
    {
        const float* qa = &g_Q[(q0 + warp * 16 + gid) * D];
        const float* qb = qa + 8 * D;
        #pragma unroll
        for (int kg = 0; kg < 4; kg++) {
            int d0 = kg * 16 + 2 * tig;
            #pragma unroll
            for (int hf = 0; hf < 2; hf++) {
                float va0 = qa[d0 + hf * 8], va1 = qa[d0 + hf * 8 + 1];
                float vb0 = qb[d0 + hf * 8], vb1 = qb[d0 + hf * 8 + 1];
                __half2 ha = __floats2half2_rn(va0, va1);
                __half2 hb = __floats2half2_rn(vb0, vb1);
                float2 fa = __half22float2(ha), fb = __half22float2(hb);
                qh[kg][hf * 2 + 0] = h2bits(ha); qh[kg][hf * 2 + 1] = h2bits(hb);
                ql[kg][hf * 2 + 0] = packh2(va0 - fa.x, va1 - fa.y);
                ql[kg][hf * 2 + 1] = packh2(vb0 - fb.x, vb1 - fb.y);
            }
        }
    }

    float oacc[8][4];
    #pragma unroll
    for (int dt = 0; dt < 8; dt++)
        #pragma unroll
        for (int c = 0; c < 4; c++) oacc[dt][c] = 0.0f;
    float mA = -INFINITY, mB = -INFINITY, lA = 0.0f, lB = 0.0f;

    load_tiles(sbase, n_begin, tid);
    CP_COMMIT();

    const uint32_t fragoff = (uint32_t)gid * 32 + (uint32_t)tig * 8;   // V frags
    const uint32_t kcoff   = (uint32_t)gid * 64 + (uint32_t)tig * 16;  // fused K frags

    for (int i = 0; i < NITER; i++) {
        const uint32_t sb = sbase + (uint32_t)(i & 1) * BUF_BYTES;
        CP_WAIT0();
        __syncthreads();
        if (i + 1 < NITER)
            load_tiles(sbase + (uint32_t)((i + 1) & 1) * BUF_BYTES,
                       n_begin + (i + 1) * BN, tid);
        CP_COMMIT();

        // ---- S = Qh*Kh + Ql*Kh + Qh*Kl  (fused KhKl: one LDS.128 per frag) ----
        float sacc[16][4];
        #pragma unroll
        for (int nt = 0; nt < 16; nt++)
            #pragma unroll
            for (int c = 0; c < 4; c++) sacc[nt][c] = 0.0f;

        #pragma unroll
        for (int kg = 0; kg < 4; kg++) {
            #pragma unroll
            for (int nt = 0; nt < 16; nt++) {
                uint4 kk = lds128(sb + (uint32_t)kg * 8192 + (uint32_t)nt * 512 + kcoff);
                mma16(sacc[nt], qh[kg], kk.x, kk.y);
                mma16(sacc[nt], ql[kg], kk.x, kk.y);
                mma16(sacc[nt], qh[kg], kk.z, kk.w);
            }
        }

        // ---- online softmax; P = ex2.f16x2 directly in fp16 registers ----
        float mxA = -INFINITY, mxB = -INFINITY;
        #pragma unroll
        for (int nt = 0; nt < 16; nt++) {
            mxA = fmaxf(mxA, fmaxf(sacc[nt][0], sacc[nt][1]));
            mxB = fmaxf(mxB, fmaxf(sacc[nt][2], sacc[nt][3]));
        }
        mxA = fmaxf(mxA, __shfl_xor_sync(0xffffffffu, mxA, 1));
        mxA = fmaxf(mxA, __shfl_xor_sync(0xffffffffu, mxA, 2));
        mxB = fmaxf(mxB, __shfl_xor_sync(0xffffffffu, mxB, 1));
        mxB = fmaxf(mxB, __shfl_xor_sync(0xffffffffu, mxB, 2));
        float mnA = fmaxf(mA, mxA), mnB = fmaxf(mB, mxB);
        float alA = ex2(mA - mnA),  alB = ex2(mB - mnB);
        mA = mnA; mB = mnB;

        uint32_t pf0[16], pf1[16];
        float sumA = 0.0f, sumB = 0.0f;
        #pragma unroll
        for (int nt = 0; nt < 16; nt++) {
            uint32_t xa = packh2(sacc[nt][0] - mnA, sacc[nt][1] - mnA);
            uint32_t xb = packh2(sacc[nt][2] - mnB, sacc[nt][3] - mnB);
            pf0[nt] = ex2h2(xa);
            pf1[nt] = ex2h2(xb);
            float2 f01 = __half22float2(*reinterpret_cast<__half2*>(&pf0[nt]));
            float2 f23 = __half22float2(*reinterpret_cast<__half2*>(&pf1[nt]));
            sumA += f01.x + f01.y;
            sumB += f23.x + f23.y;
        }
        sumA += __shfl_xor_sync(0xffffffffu, sumA, 1);
        sumA += __shfl_xor_sync(0xffffffffu, sumA, 2);
        sumB += __shfl_xor_sync(0xffffffffu, sumB, 1);
        sumB += __shfl_xor_sync(0xffffffffu, sumB, 2);
        lA = lA * alA + sumA;
        lB = lB * alB + sumB;

        #pragma unroll
        for (int dt = 0; dt < 8; dt++) {
            oacc[dt][0] *= alA; oacc[dt][1] *= alA;
            oacc[dt][2] *= alB; oacc[dt][3] *= alB;
        }

        // ---- O += P * Vh  (A-frag = packed S D-frags, register-resident) ----
        #pragma unroll
        for (int kg = 0; kg < 8; kg++) {
            uint32_t pa[4] = { pf0[2 * kg], pf1[2 * kg], pf0[2 * kg + 1], pf1[2 * kg + 1] };
            #pragma unroll
            for (int dt = 0; dt < 8; dt++) {
                uint2 vhb = lds64(sb + VOFF + (uint32_t)kg * 2048 + (uint32_t)dt * 256 + fragoff);
                mma16(oacc[dt], pa, vhb.x, vhb.y);
            }
        }
    }

    // ---- epilogue: unnormalized partials + stats ----
    int rowA = q0 + warp * 16 + gid;
    int rowB = rowA + 8;
    #pragma unroll
    for (int dt = 0; dt < 8; dt++) {
        *reinterpret_cast<float2*>(&g_Op[split][rowA * D + dt * 8 + 2 * tig]) =
            make_float2(oacc[dt][0], oacc[dt][1]);
        *reinterpret_cast<float2*>(&g_Op[split][rowB * D + dt * 8 + 2 * tig]) =
            make_float2(oacc[dt][2], oacc[dt][3]);
    }
    if (tig == 0) {
        g_ms[split][rowA] = mA; g_ls[split][rowA] = lA;
        g_ms[split][rowB] = mB; g_ls[split][rowB] = lB;
    }
}

// ============================================================================
// Merge the NSPLIT partials (stats in log2 units -> ex2).
// ============================================================================
__global__ __launch_bounds__(256) void merge_kernel(float* __restrict__ out)
{
    int idx = blockIdx.x * 256 + threadIdx.x;
    int row = idx >> 6;
    float m0 = g_ms[0][row], m1 = g_ms[1][row];
    float m = fmaxf(m0, m1);
    float e0 = ex2(m0 - m), e1 = ex2(m1 - m);
    float denom = e0 * g_ls[0][row] + e1 * g_ls[1][row];
    out[idx] = (e0 * g_Op[0][idx] + e1 * g_Op[1][idx]) / denom;
}

extern "C" void kernel_launch(void* const* d_in, const int* in_sizes, int n_in,
                              void* d_out, int out_size) {
    (void)in_sizes; (void)n_in; (void)out_size;
    const float* X  = (const float*)d_in[0];
    const float* Wq = (const float*)d_in[1];
    const float* Wk = (const float*)d_in[2];
    const float* Wv = (const float*)d_in[3];
    float* out = (float*)d_out;

    cudaFuncSetAttribute(attn_kernel,
                         cudaFuncAttributeMaxDynamicSharedMemorySize, ATTN_SMEM_BYTES);

    wconv_kernel<<<(256 * NCOL) / 256, 256>>>(Wq, Wk, Wv);
    qkv_tensor<<<SEQ / 64, 512>>>(X);

    dim3 gattn(SEQ / BM, NSPLIT);
    attn_kernel<<<gattn, 128, ATTN_SMEM_BYTES>>>();

    merge_kernel<<<SEQ * D / 256, 256>>>(out);
}